// round 7
// baseline (speedup 1.0000x reference)
#include <cuda_runtime.h>
#include <math.h>

#define TWO_PI 6.283185307179586f
#define EPS 1e-6f
#define NEG_HALF_LOG2E (-0.7213475204444817f)

typedef unsigned long long u64;

// ---------------- device scratch ----------------
#define MAXM 120000
#define MAXS 4096
#define MAXROWS 320

__device__ float g_PX[MAXM], g_PY[MAXM];
__device__ float g_C00[MAXM], g_C01[MAXM], g_C10[MAXM], g_C11[MAXM];
__device__ float g_W2[MAXM];

__device__ float g_SW[MAXS], g_SPX[MAXS], g_SPY[MAXS];
__device__ float g_SC00[MAXS], g_SC01[MAXS], g_SC10[MAXS], g_SC11[MAXS];

__device__ float g_TOT[MAXROWS], g_SIG[MAXROWS];
__device__ int g_tick = 0;

__device__ __forceinline__ float fast_exp2(float x) {
    float y; asm("ex2.approx.ftz.f32 %0, %1;" : "=f"(y) : "f"(x)); return y;
}
__device__ __forceinline__ float fast_sqrt(float x) {
    float y; asm("sqrt.approx.ftz.f32 %0, %1;" : "=f"(y) : "f"(x)); return y;
}
__device__ __forceinline__ float fast_rcp(float x) {
    float y; asm("rcp.approx.ftz.f32 %0, %1;" : "=f"(y) : "f"(x)); return y;
}

// ---- packed f32x2 helpers ----
__device__ __forceinline__ u64 pk2(float lo, float hi) {
    u64 r; asm("mov.b64 %0, {%1, %2};" : "=l"(r) : "f"(lo), "f"(hi)); return r;
}
__device__ __forceinline__ void upk2(u64 v, float& lo, float& hi) {
    asm("mov.b64 {%0, %1}, %2;" : "=f"(lo), "=f"(hi) : "l"(v));
}
__device__ __forceinline__ u64 add2(u64 a, u64 b) {
    u64 r; asm("add.rn.f32x2 %0, %1, %2;" : "=l"(r) : "l"(a), "l"(b)); return r;
}
__device__ __forceinline__ u64 mul2(u64 a, u64 b) {
    u64 r; asm("mul.rn.f32x2 %0, %1, %2;" : "=l"(r) : "l"(a), "l"(b)); return r;
}
__device__ __forceinline__ u64 fma2(u64 a, u64 b, u64 c) {
    u64 r; asm("fma.rn.f32x2 %0, %1, %2, %3;" : "=l"(r) : "l"(a), "l"(b), "l"(c)); return r;
}

// ================= fused conv + eval =================
// grid: (chunks, rows=B*Lo), block 256. Each block:
//  1) bn prologue (input bn for first layer, per-li scale otherwise)
//  2) conv phase: compute all N components of this row into packed shared tile;
//     chunk-0 blocks also write px/py/C to global for topk's gather
//  3) eval phase: this block's 256 k's -> w2 -> g_W2
__global__ __launch_bounds__(256) void k_conveval(
    const float* __restrict__ in_x, const float* __restrict__ kern,
    const float* __restrict__ bias,
    int Li, int Nd, int Lo, int Nk, int N, int first)
{
    extern __shared__ __align__(16) float sh[];
    const int Npad = (N + 1) & ~1;
    const int half = Npad >> 1;
    float* sAf = sh;            // (px,px,py,py) pairs
    float* sBf = sh + 2 * Npad; // (ea,ea,eb,eb)
    float* sCf = sh + 4 * Npad; // (ec,ec,w,w)
    __shared__ float s_scl[8];
    __shared__ float s_red[64];

    const int tid = threadIdx.x;
    const int row = blockIdx.y;
    const int b = row / Lo, lo = row % Lo;

    // ---- bn prologue ----
    if (first) {
        if (tid < 64) {
            const float* m = in_x + (b * 64 + tid) * 7;
            float det = m[3] * m[6] - m[4] * m[5];
            s_red[tid] = fabsf(m[0] * TWO_PI * fast_sqrt(fmaxf(det, EPS)));
        }
        __syncthreads();
        if (tid < 32) {
            float v = s_red[tid] + s_red[tid + 32];
            for (int o = 16; o > 0; o >>= 1) v += __shfl_xor_sync(0xffffffffu, v, o);
            if (tid == 0) s_scl[0] = 1.0f / (v + EPS);
        }
    } else {
        if (tid < Li * 32) {
            int li = tid >> 5, bb = tid & 31;
            float v = g_TOT[bb * Li + li];
            for (int o = 16; o > 0; o >>= 1) v += __shfl_xor_sync(0xffffffffu, v, o);
            if ((tid & 31) == 0) s_scl[li] = 1.0f / (v * (1.0f / 32.0f) + EPS);
        }
    }
    __syncthreads();

    // ---- conv phase: full row tile into shared ----
    const int NdNk = Nd * Nk;
    const int rowbase = row * N;
    for (int i = tid; i < Npad; i += 256) {
        float psx = 0, psy = 0, ea = 0, eb = 0, ec = 0, ws = 0;
        if (i < N) {
            int nk = i % Nk; int di_loc = i / Nk; int li = di_loc / Nd;
            int di = b * Li * Nd + di_loc;
            float wd, pdx, pdy, d00, d01, d10, d11;
            if (first) {
                const float* m = in_x + di * 7;
                wd = m[0] * s_scl[0]; pdx = m[1]; pdy = m[2];
                d00 = m[3]; d01 = m[4]; d10 = m[5]; d11 = m[6];
            } else {
                wd = g_SW[di] * s_scl[li];
                pdx = g_SPX[di]; pdy = g_SPY[di];
                d00 = g_SC00[di]; d01 = g_SC01[di];
                d10 = g_SC10[di]; d11 = g_SC11[di];
            }
            const float* kp = kern + (((lo * Li + li) * Nk) + nk) * 7;
            float wk = kp[0];
            float s00 = d00 + kp[3], s01 = d01 + kp[4];
            float s10 = d10 + kp[5], s11 = d11 + kp[6];
            float dd = d00 * d11 - d01 * d10;
            float dk = kp[3] * kp[6] - kp[4] * kp[5];
            float ds = s00 * s11 - s01 * s10;
            float inv = fast_rcp(fmaxf(ds, EPS));
            ws = wd * wk * TWO_PI * fast_sqrt(dd * dk * inv);
            psx = pdx + kp[1]; psy = pdy + kp[2];
            ea = NEG_HALF_LOG2E * s11 * inv;
            eb = -NEG_HALF_LOG2E * (s01 + s10) * inv;
            ec = NEG_HALF_LOG2E * s00 * inv;
            if (blockIdx.x == 0) {
                int o = rowbase + i;
                g_PX[o] = psx; g_PY[o] = psy;
                g_C00[o] = s00; g_C01[o] = s01;
                g_C10[o] = s10; g_C11[o] = s11;
            }
        }
        int j4 = (i >> 1) * 4 + (i & 1);
        sAf[j4] = psx; sAf[j4 + 2] = psy;
        sBf[j4] = ea;  sBf[j4 + 2] = eb;
        sCf[j4] = ec;  sCf[j4 + 2] = ws;
    }
    __syncthreads();

    // ---- eval phase ----
    int k = blockIdx.x * 256 + tid;
    if (k >= N) return;

    int k4 = (k >> 1) * 4 + (k & 1);
    float kx = sAf[k4], ky = sAf[k4 + 2];
    float wk = sCf[k4 + 2];
    u64 nkx2 = pk2(-kx, -kx);
    u64 nky2 = pk2(-ky, -ky);
    u64 acc = 0ull;

    const float4* sA = (const float4*)sAf;
    const float4* sB = (const float4*)sBf;
    const float4* sC = (const float4*)sCf;

    #pragma unroll 4
    for (int j = 0; j < half; j++) {
        float4 a = sA[j];
        float4 bq = sB[j];
        float4 c = sC[j];
        u64 px2 = *(const u64*)&a.x;  u64 py2 = *(const u64*)&a.z;
        u64 ea2 = *(const u64*)&bq.x; u64 eb2 = *(const u64*)&bq.z;
        u64 ec2 = *(const u64*)&c.x;  u64 w2p = *(const u64*)&c.z;

        u64 dx = add2(px2, nkx2);
        u64 dy = add2(py2, nky2);
        u64 u  = fma2(ea2, dx, mul2(eb2, dy));
        u64 md = fma2(dx, u, mul2(mul2(ec2, dy), dy));
        float m0, m1; upk2(md, m0, m1);
        u64 e = pk2(fast_exp2(m0), fast_exp2(m1));
        acc = fma2(w2p, e, acc);
    }

    float a0, a1; upk2(acc, a0, a1);
    float v = a0 + a1 + bias[lo];
    float scale = fmaxf(v, 0.0f) * fast_rcp(fabsf(v) + EPS);
    g_W2[rowbase + k] = wk * scale;
}

// ---------------- two-level rank top-k: one block per row ----------------
__global__ void k_topk(int N, int nchunks, int nsel, int do_final, int rows,
                       float* __restrict__ out) {
    const int tid = threadIdx.x;
    const int row = blockIdx.x;
    const int base = row * N;
    const int NC = nchunks * 64;

    __shared__ __align__(16) u64 keys[640];
    __shared__ __align__(16) u64 sCand[136];
    __shared__ int s_cnt;
    __shared__ float s_out[64];
    __shared__ int s_last;
    __shared__ float scl[10];
    __shared__ float logit[320];

    if (tid == 0) s_cnt = 0;
    for (int n = tid; n < NC; n += blockDim.x) {
        keys[n] = (n < N)
            ? (((u64)__float_as_uint(fabsf(g_W2[base + n])) << 32) | (u64)(unsigned)(~(unsigned)n))
            : 0ull;
    }
    __syncthreads();

    // level 1: per-warp chunk rank
    {
        int w = tid >> 5, lane = tid & 31;
        int kb = w << 6;
        u64 k0 = keys[kb + lane];
        u64 k1 = keys[kb + lane + 32];
        int r0 = 0, r1 = 0;
        const ulonglong2* Q = (const ulonglong2*)(keys + kb);
        #pragma unroll 8
        for (int j = 0; j < 32; j++) {
            ulonglong2 q = Q[j];
            r0 += (int)(q.x > k0) + (int)(q.y > k0);
            r1 += (int)(q.x > k1) + (int)(q.y > k1);
        }
        if (kb + lane < N && r0 < nsel)      { int s = atomicAdd(&s_cnt, 1); sCand[s] = k0; }
        if (kb + lane + 32 < N && r1 < nsel) { int s = atomicAdd(&s_cnt, 1); sCand[s] = k1; }
    }
    __syncthreads();
    int m = s_cnt;
    if (tid == 0 && (m & 1)) sCand[m] = 0ull;
    __syncthreads();

    // level 2: exact rank among candidates
    {
        int mq = (m + 1) >> 1;
        const ulonglong2* Q = (const ulonglong2*)sCand;
        for (int i = tid; i < m; i += blockDim.x) {
            u64 mykey = sCand[i];
            int rank = 0;
            #pragma unroll 4
            for (int j = 0; j < mq; j++) {
                ulonglong2 q = Q[j];
                rank += (int)(q.x > mykey) + (int)(q.y > mykey);
            }
            if (rank < nsel) {
                int n = (int)(~(unsigned)mykey);
                int src = base + n;
                int dst = row * nsel + rank;
                float wv = g_W2[src];
                float c00 = g_C00[src], c01 = g_C01[src], c10 = g_C10[src], c11 = g_C11[src];
                g_SW[dst] = wv;
                g_SPX[dst] = g_PX[src]; g_SPY[dst] = g_PY[src];
                g_SC00[dst] = c00; g_SC01[dst] = c01;
                g_SC10[dst] = c10; g_SC11[dst] = c11;
                float I = wv * TWO_PI * fast_sqrt(fmaxf(c00 * c11 - c01 * c10, EPS));
                s_out[rank] = fabsf(I);
                s_out[32 + rank] = I;
            }
        }
    }
    __syncthreads();
    if (tid == 0) {
        float tot = 0.0f, sg = 0.0f;
        for (int t = 0; t < nsel; t++) { tot += s_out[t]; sg += s_out[32 + t]; }
        g_TOT[row] = tot;
        if (do_final) g_SIG[row] = sg;
    }

    if (!do_final) return;

    // fused finale
    if (tid == 0) {
        __threadfence();
        int t = atomicAdd(&g_tick, 1);
        s_last = (t == rows - 1) ? 1 : 0;
        if (s_last) g_tick = 0;
    }
    __syncthreads();
    if (!s_last) return;
    __threadfence();

    if (tid < 10) {
        float t = 0.0f;
        for (int b = 0; b < 32; b++) t += g_TOT[b * 10 + tid];
        scl[tid] = 1.0f / (t / 32.0f + EPS);
    }
    __syncthreads();
    for (int i = tid; i < 320; i += blockDim.x) logit[i] = g_SIG[i] * scl[i % 10];
    __syncthreads();
    if (tid < 32) {
        int b = tid;
        float mx = -INFINITY;
        for (int l = 0; l < 10; l++) mx = fmaxf(mx, logit[b * 10 + l]);
        float se = 0.0f;
        for (int l = 0; l < 10; l++) se += expf(logit[b * 10 + l] - mx);
        float lse = mx + logf(se);
        for (int l = 0; l < 10; l++) out[b * 10 + l] = logit[b * 10 + l] - lse;
    }
}

extern "C" void kernel_launch(void* const* d_in, const int* in_sizes, int n_in,
                              void* d_out, int out_size) {
    const float* in_x = (const float*)d_in[0];
    const float* k1 = (const float*)d_in[1];
    const float* k2 = (const float*)d_in[2];
    const float* k3 = (const float*)d_in[3];
    const float* b1 = (const float*)d_in[4];
    const float* b2 = (const float*)d_in[5];
    const float* b3 = (const float*)d_in[6];
    float* out = (float*)d_out;
    const int B = 32;

    // ===== layer 1: Li=1, Nd=64, Lo=5, Nk=5 -> N=320, rows=160, nsel=25 =====
    {
        int Li = 1, Nd = 64, Lo = 5, Nk = 5;
        int N = Li * Nd * Nk, rows = B * Lo;
        int Np = (N + 1) & ~1, nch = (N + 63) / 64;
        k_conveval<<<dim3((N + 255) / 256, rows), 256, Np * 24>>>(
            in_x, k1, b1, Li, Nd, Lo, Nk, N, 1);
        k_topk<<<rows, 32 * nch>>>(N, nch, 25, 0, rows, out);
    }

    // ===== layer 2: Li=5, Nd=25, Lo=6, Nk=5 -> N=625, rows=192, nsel=12 =====
    {
        int Li = 5, Nd = 25, Lo = 6, Nk = 5;
        int N = Li * Nd * Nk, rows = B * Lo;
        int Np = (N + 1) & ~1, nch = (N + 63) / 64;
        k_conveval<<<dim3((N + 255) / 256, rows), 256, Np * 24>>>(
            in_x, k2, b2, Li, Nd, Lo, Nk, N, 0);
        k_topk<<<rows, 32 * nch>>>(N, nch, 12, 0, rows, out);
    }

    // ===== layer 3: Li=6, Nd=12, Lo=10, Nk=5 -> N=360, rows=320, nsel=5 =====
    {
        int Li = 6, Nd = 12, Lo = 10, Nk = 5;
        int N = Li * Nd * Nk, rows = B * Lo;
        int Np = (N + 1) & ~1, nch = (N + 63) / 64;
        k_conveval<<<dim3((N + 255) / 256, rows), 256, Np * 24>>>(
            in_x, k3, b3, Li, Nd, Lo, Nk, N, 0);
        k_topk<<<rows, 32 * nch>>>(N, nch, 5, 1, rows, out);
    }
}